// round 8
// baseline (speedup 1.0000x reference)
#include <cuda_runtime.h>
#include <cuda_bf16.h>
#include <cstdint>

#define B_TOT 1024
#define NW 64

__device__ float g_bm[NW * 8 * 128 * 128];      // bias+mask [w][h][n][j]  (32MB)
__device__ float g_xo[B_TOT * 128 * 128];       // attn output fp32 (64MB)
// packed weight fragments: [tile][ks][lane] -> {pair kp, pair kp+4}
__device__ uint2 g_Pc_h[48 * 8 * 32];           // qkv combined W^T, 3-way split
__device__ uint2 g_Pc_m[48 * 8 * 32];
__device__ uint2 g_Pc_l[48 * 8 * 32];
__device__ uint2 g_Pp_h[16 * 8 * 32];           // proj W^T, 2-way split
__device__ uint2 g_Pp_m[16 * 8 * 32];

__device__ __forceinline__ unsigned short bfb(__nv_bfloat16 h) { return *reinterpret_cast<unsigned short*>(&h); }

__device__ __forceinline__ void split3s(float v, unsigned short& h, unsigned short& m, unsigned short& l) {
    __nv_bfloat16 bh = __float2bfloat16(v);
    float r1 = v - __bfloat162float(bh);
    __nv_bfloat16 bm = __float2bfloat16(r1);
    float r2 = r1 - __bfloat162float(bm);
    h = bfb(bh); m = bfb(bm); l = bfb(__float2bfloat16(r2));
}

__device__ __forceinline__ void hmma(float* d, const uint32_t* a, const uint32_t* b) {
    asm volatile("mma.sync.aligned.m16n8k16.row.col.f32.bf16.bf16.f32 "
                 "{%0,%1,%2,%3},{%4,%5,%6,%7},{%8,%9},{%0,%1,%2,%3};"
                 : "+f"(d[0]), "+f"(d[1]), "+f"(d[2]), "+f"(d[3])
                 : "r"(a[0]), "r"(a[1]), "r"(a[2]), "r"(a[3]), "r"(b[0]), "r"(b[1]));
}

// ---------------- prep ----------------
__global__ void prep_bm(const float* __restrict__ mask, const float* __restrict__ tbl,
                        const int* __restrict__ rel) {
    int t = blockIdx.x * blockDim.x + threadIdx.x;
    if (t >= NW * 16384) return;
    int w = t >> 14, nj = t & 16383;
    int r = rel[nj];
    float mk = mask[t];
#pragma unroll
    for (int h = 0; h < 8; h++)
        g_bm[(((w << 3) + h) << 14) + nj] = tbl[r * 8 + h] + mk;
}

__global__ void prep_w(const float* __restrict__ Wq, const float* __restrict__ Wkv,
                       const float* __restrict__ Wp) {
    int t = blockIdx.x * blockDim.x + threadIdx.x;   // < 16384
    int lane = t & 31, rest = t >> 5;
    int ks = rest & 7, tile = rest >> 3;
    int lr = lane >> 2, lc = lane & 3;
    int kb = ks * 16 + lc * 2;
    int kk[4] = { kb, kb + 1, kb + 8, kb + 9 };
    if (tile < 48) {
        int n = tile * 8 + lr;
        unsigned short h[4], m[4], l[4];
#pragma unroll
        for (int i = 0; i < 4; i++) {
            int k = kk[i];
            float v = (n < 128) ? Wq[k * 128 + n] * 0.25f : Wkv[k * 256 + (n - 128)];
            split3s(v, h[i], m[i], l[i]);
        }
        int idx = (tile * 8 + ks) * 32 + lane;
        g_Pc_h[idx] = make_uint2((uint32_t)h[0] | ((uint32_t)h[1] << 16),
                                 (uint32_t)h[2] | ((uint32_t)h[3] << 16));
        g_Pc_m[idx] = make_uint2((uint32_t)m[0] | ((uint32_t)m[1] << 16),
                                 (uint32_t)m[2] | ((uint32_t)m[3] << 16));
        g_Pc_l[idx] = make_uint2((uint32_t)l[0] | ((uint32_t)l[1] << 16),
                                 (uint32_t)l[2] | ((uint32_t)l[3] << 16));
    } else if (tile < 64) {
        int n = (tile - 48) * 8 + lr;
        unsigned short h[4], m[4], l[4];
#pragma unroll
        for (int i = 0; i < 4; i++)
            split3s(Wp[kk[i] * 128 + n], h[i], m[i], l[i]);
        int idx = ((tile - 48) * 8 + ks) * 32 + lane;
        g_Pp_h[idx] = make_uint2((uint32_t)h[0] | ((uint32_t)h[1] << 16),
                                 (uint32_t)h[2] | ((uint32_t)h[3] << 16));
        g_Pp_m[idx] = make_uint2((uint32_t)m[0] | ((uint32_t)m[1] << 16),
                                 (uint32_t)m[2] | ((uint32_t)m[3] << 16));
    }
}

// ---------------- fused attention (1024 threads) ----------------
// smem bytes: XH@0 XM@32768 XL@65536 (u32[128][64], swizzled)
//             K@98304 (f32 pitch130, 66560B)  V@164864 (same)   total 231424
// Q overlays X region after phase A (f32 pitch132, 67584B)
#define SM_XM 32768
#define SM_XL 65536
#define SM_K  98304
#define SM_V  164864
#define ATTN_SMEM 231424
#define PQ 132
#define PK 130
#define PV 130

__global__ __launch_bounds__(1024, 1)
void attn_kernel(const float* __restrict__ x) {
    extern __shared__ char sm[];
    uint32_t* XH = reinterpret_cast<uint32_t*>(sm);
    uint32_t* XM = reinterpret_cast<uint32_t*>(sm + SM_XM);
    uint32_t* XL = reinterpret_cast<uint32_t*>(sm + SM_XL);
    float* sQ = reinterpret_cast<float*>(sm);
    float* sK = reinterpret_cast<float*>(sm + SM_K);
    float* sV = reinterpret_cast<float*>(sm + SM_V);

    const int b = blockIdx.x, tid = threadIdx.x;
    const int wid = tid >> 5, lane = tid & 31;

    // stage x -> 3-way bf16 split, swizzled pitch 64
    const float* xb = x + b * 16384;
    for (int p = tid; p < 8192; p += 1024) {
        int row = p >> 6, kp = p & 63;
        float2 v = *reinterpret_cast<const float2*>(xb + row * 128 + kp * 2);
        unsigned short h0, m0, l0, h1, m1, l1;
        split3s(v.x, h0, m0, l0);
        split3s(v.y, h1, m1, l1);
        int idx = row * 64 + (kp ^ ((row & 7) << 2));
        XH[idx] = (uint32_t)h0 | ((uint32_t)h1 << 16);
        XM[idx] = (uint32_t)m0 | ((uint32_t)m1 << 16);
        XL[idx] = (uint32_t)l0 | ((uint32_t)l1 << 16);
    }
    __syncthreads();

    // ---- phase A: QKV GEMM via HMMA; 32 warps = mt(8) x np(4), 4 tiles/warp/grp
    const int mt = wid & 7, np = wid >> 3, lr = lane >> 2, lc = lane & 3;
    const int sw = lr << 2;
    const int r0 = (mt * 16 + lr) * 64;
    const int r1 = r0 + 8 * 64;
    float CQ[4][4];

#pragma unroll
    for (int grp = 0; grp < 3; grp++) {
        const int ibase = (grp == 0) ? 4 : (grp == 1) ? 8 : 0;   // K, V, Q
        float C[4][4];
#pragma unroll
        for (int t = 0; t < 4; t++) { C[t][0] = C[t][1] = C[t][2] = C[t][3] = 0.f; }
#pragma unroll 2
        for (int ks = 0; ks < 8; ks++) {
            const int k0 = (ks * 8 + lc) ^ sw;
            const int k1 = (ks * 8 + lc + 4) ^ sw;
            uint32_t ah[4], am[4], al[4];
            ah[0] = XH[r0 + k0]; ah[1] = XH[r1 + k0]; ah[2] = XH[r0 + k1]; ah[3] = XH[r1 + k1];
            am[0] = XM[r0 + k0]; am[1] = XM[r1 + k0]; am[2] = XM[r0 + k1]; am[3] = XM[r1 + k1];
            if (grp != 1) {
                al[0] = XL[r0 + k0]; al[1] = XL[r1 + k0]; al[2] = XL[r0 + k1]; al[3] = XL[r1 + k1];
            }
#pragma unroll
            for (int t = 0; t < 4; t++) {
                const int tile = np + 4 * (ibase + t);
                const int fi = (tile * 8 + ks) * 32 + lane;
                uint2 h2 = __ldg(&g_Pc_h[fi]);
                uint2 m2 = __ldg(&g_Pc_m[fi]);
                uint32_t bh[2] = { h2.x, h2.y };
                uint32_t bm[2] = { m2.x, m2.y };
                hmma(C[t], ah, bh);
                hmma(C[t], ah, bm);
                hmma(C[t], am, bh);
                if (grp != 1) {
                    uint2 l2 = __ldg(&g_Pc_l[fi]);
                    uint32_t bl[2] = { l2.x, l2.y };
                    hmma(C[t], am, bm);
                    hmma(C[t], ah, bl);
                    hmma(C[t], al, bh);
                }
            }
        }
        if (grp == 2) {
#pragma unroll
            for (int t = 0; t < 4; t++) {
                CQ[t][0] = C[t][0]; CQ[t][1] = C[t][1];
                CQ[t][2] = C[t][2]; CQ[t][3] = C[t][3];
            }
        } else {
            float* dst = (grp == 0) ? sK : sV;
            const int pitch = (grp == 0) ? PK : PV;
            const int coff = (grp == 0) ? 128 : 256;
#pragma unroll
            for (int t = 0; t < 4; t++) {
                const int col = (np + 4 * (ibase + t)) * 8 + lc * 2 - coff;
                const int row = mt * 16 + lr;
                *reinterpret_cast<float2*>(dst + row * pitch + col) = make_float2(C[t][0], C[t][1]);
                *reinterpret_cast<float2*>(dst + (row + 8) * pitch + col) = make_float2(C[t][2], C[t][3]);
            }
        }
    }
    __syncthreads();     // all x reads complete before Q overlays X
#pragma unroll
    for (int t = 0; t < 4; t++) {
        const int col = (np + 4 * t) * 8 + lc * 2;
        const int row = mt * 16 + lr;
        *reinterpret_cast<float2*>(sQ + row * PQ + col) = make_float2(CQ[t][0], CQ[t][1]);
        *reinterpret_cast<float2*>(sQ + (row + 8) * PQ + col) = make_float2(CQ[t][2], CQ[t][3]);
    }
    __syncthreads();

    // ---- phase B: logits + branchless top-2; 32 warps = h(8) x nquarter(4), 32 rows/warp
    const int h = wid >> 2, c0 = h * 16, nb = (wid & 3) * 32;
    const float* bmh = g_bm + ((((b & 63) << 3) + h) << 14);
    float* xoB = g_xo + (b << 14);

    for (int g = 0; g < 16; g++) {
        const int n = nb + g * 2;
        float4 qa[2][4];
#pragma unroll
        for (int r = 0; r < 2; r++)
#pragma unroll
            for (int u = 0; u < 4; u++)
                qa[r][u] = *reinterpret_cast<const float4*>(&sQ[(n + r) * PQ + c0 + u * 4]);

        float sc[2][4];
        float m1[2] = { -3e38f, -3e38f }, m2[2] = { -3e38f, -3e38f };
        int i1[2] = { 0, 0 }, i2[2] = { 0, 0 };
#pragma unroll
        for (int jj = 0; jj < 4; jj++) {
            const int j = jj * 32 + lane;
            const float2* kr = reinterpret_cast<const float2*>(sK + j * PK + c0);
            float2 k0 = kr[0], k1 = kr[1], k2 = kr[2], k3 = kr[3];
            float2 k4 = kr[4], k5 = kr[5], k6 = kr[6], k7 = kr[7];
#pragma unroll
            for (int r = 0; r < 2; r++) {
                float s = bmh[((n + r) << 7) + j];
                s = fmaf(qa[r][0].x, k0.x, s); s = fmaf(qa[r][0].y, k0.y, s);
                s = fmaf(qa[r][0].z, k1.x, s); s = fmaf(qa[r][0].w, k1.y, s);
                s = fmaf(qa[r][1].x, k2.x, s); s = fmaf(qa[r][1].y, k2.y, s);
                s = fmaf(qa[r][1].z, k3.x, s); s = fmaf(qa[r][1].w, k3.y, s);
                s = fmaf(qa[r][2].x, k4.x, s); s = fmaf(qa[r][2].y, k4.y, s);
                s = fmaf(qa[r][2].z, k5.x, s); s = fmaf(qa[r][2].w, k5.y, s);
                s = fmaf(qa[r][3].x, k6.x, s); s = fmaf(qa[r][3].y, k6.y, s);
                s = fmaf(qa[r][3].z, k7.x, s); s = fmaf(qa[r][3].w, k7.y, s);
                sc[r][jj] = s;
                bool g1 = s > m1[r], g2 = s > m2[r];
                float om1 = m1[r]; int oi1 = i1[r];
                m2[r] = g1 ? om1 : (g2 ? s : m2[r]);
                i2[r] = g1 ? oi1 : (g2 ? j : i2[r]);
                m1[r] = g1 ? s : om1;
                i1[r] = g1 ? j : oi1;
            }
        }
#pragma unroll
        for (int r = 0; r < 2; r++) {
            float a1 = m1[r], a2 = m2[r];
            int ai1 = i1[r], ai2 = i2[r];
#pragma unroll
            for (int off = 16; off; off >>= 1) {
                float b1 = __shfl_xor_sync(0xFFFFFFFFu, a1, off);
                int  bi1 = __shfl_xor_sync(0xFFFFFFFFu, ai1, off);
                float b2 = __shfl_xor_sync(0xFFFFFFFFu, a2, off);
                int  bi2 = __shfl_xor_sync(0xFFFFFFFFu, ai2, off);
                bool agt = (a1 > b1) || (a1 == b1 && ai1 < bi1);
                float w2 = agt ? a2 : b2; int wi2 = agt ? ai2 : bi2;
                float l1 = agt ? b1 : a1; int li1 = agt ? bi1 : ai1;
                a1 = agt ? a1 : b1; ai1 = agt ? ai1 : bi1;
                bool s2 = (w2 > l1) || (w2 == l1 && wi2 < li1);
                a2 = s2 ? w2 : l1; ai2 = s2 ? wi2 : li1;
            }
            float z = __expf(sc[r][0] - a1) + __expf(sc[r][1] - a1)
                    + __expf(sc[r][2] - a1) + __expf(sc[r][3] - a1);
#pragma unroll
            for (int off = 16; off; off >>= 1)
                z += __shfl_xor_sync(0xFFFFFFFFu, z, off);
            float inv = 1.0f / z;
            float p2 = __expf(a2 - a1) * inv;
            if (lane < 16) {
                float val = fmaf(inv, sV[ai1 * PV + c0 + lane], p2 * sV[ai2 * PV + c0 + lane]);
                xoB[((n + r) << 7) + c0 + lane] = val;
            }
        }
    }
}

// ---------------- output projection (HMMA, weights staged in smem) ----------------
#define PPX 68
#define PROJ_XL 34816
#define PROJ_WH 69632
#define PROJ_WM 102400
#define PROJ_SMEM 135168

__global__ __launch_bounds__(1024, 1)
void proj_kernel(const float* __restrict__ bp, float* __restrict__ out) {
    extern __shared__ char sm[];
    uint32_t* XH = reinterpret_cast<uint32_t*>(sm);
    uint32_t* XL = reinterpret_cast<uint32_t*>(sm + PROJ_XL);
    uint2* WH = reinterpret_cast<uint2*>(sm + PROJ_WH);
    uint2* WM = reinterpret_cast<uint2*>(sm + PROJ_WM);
    const int b = blockIdx.x, tid = threadIdx.x;
    const int wid = tid >> 5, lane = tid & 31;

    // stage weights (64KB) + x (split)
    for (int p = tid; p < 4096; p += 1024) {
        WH[p] = g_Pp_h[p];
        WM[p] = g_Pp_m[p];
    }
    const float* xb = g_xo + (b << 14);
    for (int p = tid; p < 8192; p += 1024) {
        int row = p >> 6, kp = p & 63;
        float2 v = *reinterpret_cast<const float2*>(xb + row * 128 + kp * 2);
        unsigned short h0, m0, l0, h1, m1, l1;
        split3s(v.x, h0, m0, l0);
        split3s(v.y, h1, m1, l1);
        XH[row * PPX + kp] = (uint32_t)h0 | ((uint32_t)h1 << 16);
        XL[row * PPX + kp] = (uint32_t)m0 | ((uint32_t)m1 << 16);
    }
    __syncthreads();

    const int mt = wid & 7, np = wid >> 3, lr = lane >> 2, lc = lane & 3;
    const int arow = (mt * 16 + lr) * PPX;

    float C[4][4];
#pragma unroll
    for (int t = 0; t < 4; t++) { C[t][0] = C[t][1] = C[t][2] = C[t][3] = 0.f; }
#pragma unroll 2
    for (int ks = 0; ks < 8; ks++) {
        const int ai = arow + ks * 8 + lc;
        uint32_t ah[4], al[4];
        ah[0] = XH[ai];     ah[1] = XH[ai + 8 * PPX];
        ah[2] = XH[ai + 4]; ah[3] = XH[ai + 8 * PPX + 4];
        al[0] = XL[ai];     al[1] = XL[ai + 8 * PPX];
        al[2] = XL[ai + 4]; al[3] = XL[ai + 8 * PPX + 4];
#pragma unroll
        for (int t = 0; t < 4; t++) {
            const int tile = np + 4 * t;
            const int fi = (tile * 8 + ks) * 32 + lane;
            uint2 h2 = WH[fi];
            uint2 m2 = WM[fi];
            uint32_t bh[2] = { h2.x, h2.y };
            uint32_t bm[2] = { m2.x, m2.y };
            hmma(C[t], ah, bh);
            hmma(C[t], ah, bm);
            hmma(C[t], al, bh);
        }
    }
    float* outB = out + (b << 14);
#pragma unroll
    for (int t = 0; t < 4; t++) {
        const int col = (np + 4 * t) * 8 + lc * 2;
        const int row = mt * 16 + lr;
        const float b0 = __ldg(bp + col), b1 = __ldg(bp + col + 1);
        *reinterpret_cast<float2*>(outB + row * 128 + col) = make_float2(C[t][0] + b0, C[t][1] + b1);
        *reinterpret_cast<float2*>(outB + (row + 8) * 128 + col) = make_float2(C[t][2] + b0, C[t][3] + b1);
    }
}

// ---------------------------------------------------------------------------
extern "C" void kernel_launch(void* const* d_in, const int* in_sizes, int n_in,
                              void* d_out, int out_size) {
    const float* x    = (const float*)d_in[0];
    const float* mask = (const float*)d_in[1];
    const float* Wq   = (const float*)d_in[2];
    const float* Wkv  = (const float*)d_in[3];
    const float* Wp   = (const float*)d_in[4];
    const float* bp   = (const float*)d_in[5];
    const float* tbl  = (const float*)d_in[6];
    const int*   rel  = (const int*)d_in[7];
    float* out = (float*)d_out;

    prep_w<<<32, 512>>>(Wq, Wkv, Wp);
    prep_bm<<<2048, 512>>>(mask, tbl, rel);

    cudaFuncSetAttribute(attn_kernel, cudaFuncAttributeMaxDynamicSharedMemorySize, ATTN_SMEM);
    attn_kernel<<<B_TOT, 1024, ATTN_SMEM>>>(x);

    cudaFuncSetAttribute(proj_kernel, cudaFuncAttributeMaxDynamicSharedMemorySize, PROJ_SMEM);
    proj_kernel<<<B_TOT, 1024, PROJ_SMEM>>>(bp, out);
}

// round 12
// speedup vs baseline: 1.9410x; 1.9410x over previous
#include <cuda_runtime.h>
#include <cuda_bf16.h>
#include <cstdint>

#define B_TOT 1024
#define NW 64

__device__ float g_bm[NW * 8 * 128 * 128];      // bias+mask [w][h][n][j]  (32MB)
__device__ float g_xo[B_TOT * 128 * 128];       // attn output fp32 (64MB)
// packed weight fragments: [tile][ks][lane] -> {pair kp, pair kp+4}
__device__ uint2 g_Pc_h[48 * 8 * 32];           // qkv combined W^T, 3-way split
__device__ uint2 g_Pc_m[48 * 8 * 32];
__device__ uint2 g_Pc_l[48 * 8 * 32];
__device__ uint2 g_Pp_h[16 * 8 * 32];           // proj W^T, 2-way split
__device__ uint2 g_Pp_m[16 * 8 * 32];

__device__ __forceinline__ unsigned short bfb(__nv_bfloat16 h) { return *reinterpret_cast<unsigned short*>(&h); }

__device__ __forceinline__ void split3s(float v, unsigned short& h, unsigned short& m, unsigned short& l) {
    __nv_bfloat16 bh = __float2bfloat16(v);
    float r1 = v - __bfloat162float(bh);
    __nv_bfloat16 bm = __float2bfloat16(r1);
    float r2 = r1 - __bfloat162float(bm);
    h = bfb(bh); m = bfb(bm); l = bfb(__float2bfloat16(r2));
}

__device__ __forceinline__ void hmma(float* d, const uint32_t* a, const uint32_t* b) {
    asm volatile("mma.sync.aligned.m16n8k16.row.col.f32.bf16.bf16.f32 "
                 "{%0,%1,%2,%3},{%4,%5,%6,%7},{%8,%9},{%0,%1,%2,%3};"
                 : "+f"(d[0]), "+f"(d[1]), "+f"(d[2]), "+f"(d[3])
                 : "r"(a[0]), "r"(a[1]), "r"(a[2]), "r"(a[3]), "r"(b[0]), "r"(b[1]));
}

// ---------------- prep ----------------
__global__ void prep_bm(const float* __restrict__ mask, const float* __restrict__ tbl,
                        const int* __restrict__ rel) {
    int t = blockIdx.x * blockDim.x + threadIdx.x;
    if (t >= NW * 16384) return;
    int w = t >> 14, nj = t & 16383;
    int r = rel[nj];
    float mk = mask[t];
#pragma unroll
    for (int h = 0; h < 8; h++)
        g_bm[(((w << 3) + h) << 14) + nj] = tbl[r * 8 + h] + mk;
}

__global__ void prep_w(const float* __restrict__ Wq, const float* __restrict__ Wkv,
                       const float* __restrict__ Wp) {
    int t = blockIdx.x * blockDim.x + threadIdx.x;   // < 16384
    int lane = t & 31, rest = t >> 5;
    int ks = rest & 7, tile = rest >> 3;
    int lr = lane >> 2, lc = lane & 3;
    int kb = ks * 16 + lc * 2;
    int kk[4] = { kb, kb + 1, kb + 8, kb + 9 };
    if (tile < 48) {
        int n = tile * 8 + lr;
        unsigned short h[4], m[4], l[4];
#pragma unroll
        for (int i = 0; i < 4; i++) {
            int k = kk[i];
            float v = (n < 128) ? Wq[k * 128 + n] * 0.25f : Wkv[k * 256 + (n - 128)];
            split3s(v, h[i], m[i], l[i]);
        }
        int idx = (tile * 8 + ks) * 32 + lane;
        g_Pc_h[idx] = make_uint2((uint32_t)h[0] | ((uint32_t)h[1] << 16),
                                 (uint32_t)h[2] | ((uint32_t)h[3] << 16));
        g_Pc_m[idx] = make_uint2((uint32_t)m[0] | ((uint32_t)m[1] << 16),
                                 (uint32_t)m[2] | ((uint32_t)m[3] << 16));
        g_Pc_l[idx] = make_uint2((uint32_t)l[0] | ((uint32_t)l[1] << 16),
                                 (uint32_t)l[2] | ((uint32_t)l[3] << 16));
    } else if (tile < 64) {
        int n = (tile - 48) * 8 + lr;
        unsigned short h[4], m[4], l[4];
#pragma unroll
        for (int i = 0; i < 4; i++)
            split3s(Wp[kk[i] * 128 + n], h[i], m[i], l[i]);
        int idx = ((tile - 48) * 8 + ks) * 32 + lane;
        g_Pp_h[idx] = make_uint2((uint32_t)h[0] | ((uint32_t)h[1] << 16),
                                 (uint32_t)h[2] | ((uint32_t)h[3] << 16));
        g_Pp_m[idx] = make_uint2((uint32_t)m[0] | ((uint32_t)m[1] << 16),
                                 (uint32_t)m[2] | ((uint32_t)m[3] << 16));
    }
}

// ---------------- fused attention (512 threads) ----------------
// smem bytes: XH@0 XM@32768 XL@65536 (u32[128][64], swizzled)
//             K@98304 (f32 pitch130, 66560B)  V@164864 (same)   total 231424
// Q overlays X region after phase A (f32 pitch132, 67584B)
#define SM_XM 32768
#define SM_XL 65536
#define SM_K  98304
#define SM_V  164864
#define ATTN_SMEM 231424
#define PQ 132
#define PK 130
#define PV 130

__global__ __launch_bounds__(512, 1)
void attn_kernel(const float* __restrict__ x) {
    extern __shared__ char sm[];
    uint32_t* XH = reinterpret_cast<uint32_t*>(sm);
    uint32_t* XM = reinterpret_cast<uint32_t*>(sm + SM_XM);
    uint32_t* XL = reinterpret_cast<uint32_t*>(sm + SM_XL);
    float* sQ = reinterpret_cast<float*>(sm);
    float* sK = reinterpret_cast<float*>(sm + SM_K);
    float* sV = reinterpret_cast<float*>(sm + SM_V);

    const int b = blockIdx.x, tid = threadIdx.x;
    const int wid = tid >> 5, lane = tid & 31;

    // stage x -> 3-way bf16 split, swizzled pitch 64
    const float* xb = x + b * 16384;
    for (int p = tid; p < 8192; p += 512) {
        int row = p >> 6, kp = p & 63;
        float2 v = *reinterpret_cast<const float2*>(xb + row * 128 + kp * 2);
        unsigned short h0, m0, l0, h1, m1, l1;
        split3s(v.x, h0, m0, l0);
        split3s(v.y, h1, m1, l1);
        int idx = row * 64 + (kp ^ ((row & 7) << 2));
        XH[idx] = (uint32_t)h0 | ((uint32_t)h1 << 16);
        XM[idx] = (uint32_t)m0 | ((uint32_t)m1 << 16);
        XL[idx] = (uint32_t)l0 | ((uint32_t)l1 << 16);
    }
    __syncthreads();

    // ---- phase A: QKV GEMM via HMMA; 16 warps = mt(8) x np(2), 8 tiles/warp/grp
    const int mt = wid & 7, np = wid >> 3, lr = lane >> 2, lc = lane & 3;
    const int sw = lr << 2;
    const int r0 = (mt * 16 + lr) * 64;
    const int r1 = r0 + 8 * 64;

    float C[8][4], C2[8][4];

    // grp 0 = K (6 products), grp 1 = V (3 products)
#pragma unroll
    for (int grp = 0; grp < 2; grp++) {
        const int ibase = (grp == 0) ? 8 : 16;
#pragma unroll
        for (int t = 0; t < 8; t++) {
            C[t][0] = C[t][1] = C[t][2] = C[t][3] = 0.f;
            C2[t][0] = C2[t][1] = C2[t][2] = C2[t][3] = 0.f;
        }
#pragma unroll 2
        for (int ks = 0; ks < 8; ks++) {
            const int k0 = (ks * 8 + lc) ^ sw;
            const int k1 = (ks * 8 + lc + 4) ^ sw;
            uint32_t ah[4], am[4], al[4];
            ah[0] = XH[r0 + k0]; ah[1] = XH[r1 + k0]; ah[2] = XH[r0 + k1]; ah[3] = XH[r1 + k1];
            am[0] = XM[r0 + k0]; am[1] = XM[r1 + k0]; am[2] = XM[r0 + k1]; am[3] = XM[r1 + k1];
            if (grp == 0) {
                al[0] = XL[r0 + k0]; al[1] = XL[r1 + k0]; al[2] = XL[r0 + k1]; al[3] = XL[r1 + k1];
            }
#pragma unroll
            for (int t = 0; t < 8; t++) {
                const int tile = np + 2 * (ibase + t);
                const int fi = (tile * 8 + ks) * 32 + lane;
                uint2 h2 = __ldg(&g_Pc_h[fi]);
                uint2 m2 = __ldg(&g_Pc_m[fi]);
                uint32_t bh[2] = { h2.x, h2.y };
                uint32_t bm[2] = { m2.x, m2.y };
                hmma(C[t], ah, bh);
                hmma(C2[t], ah, bm);
                hmma(C[t], am, bh);
                if (grp == 0) {
                    uint2 l2 = __ldg(&g_Pc_l[fi]);
                    uint32_t bl[2] = { l2.x, l2.y };
                    hmma(C2[t], am, bm);
                    hmma(C2[t], ah, bl);
                    hmma(C[t], al, bh);
                }
            }
        }
        float* dst = (grp == 0) ? sK : sV;
        const int pitch = (grp == 0) ? PK : PV;
        const int coff = (grp == 0) ? 128 : 256;
#pragma unroll
        for (int t = 0; t < 8; t++) {
            const int col = (np + 2 * (ibase + t)) * 8 + lc * 2 - coff;
            const int row = mt * 16 + lr;
            *reinterpret_cast<float2*>(dst + row * pitch + col) =
                make_float2(C[t][0] + C2[t][0], C[t][1] + C2[t][1]);
            *reinterpret_cast<float2*>(dst + (row + 8) * pitch + col) =
                make_float2(C[t][2] + C2[t][2], C[t][3] + C2[t][3]);
        }
    }

    // grp 2 = Q (6 products), kept in C/C2, written after sync (overlays X)
    {
#pragma unroll
        for (int t = 0; t < 8; t++) {
            C[t][0] = C[t][1] = C[t][2] = C[t][3] = 0.f;
            C2[t][0] = C2[t][1] = C2[t][2] = C2[t][3] = 0.f;
        }
#pragma unroll 2
        for (int ks = 0; ks < 8; ks++) {
            const int k0 = (ks * 8 + lc) ^ sw;
            const int k1 = (ks * 8 + lc + 4) ^ sw;
            uint32_t ah[4], am[4], al[4];
            ah[0] = XH[r0 + k0]; ah[1] = XH[r1 + k0]; ah[2] = XH[r0 + k1]; ah[3] = XH[r1 + k1];
            am[0] = XM[r0 + k0]; am[1] = XM[r1 + k0]; am[2] = XM[r0 + k1]; am[3] = XM[r1 + k1];
            al[0] = XL[r0 + k0]; al[1] = XL[r1 + k0]; al[2] = XL[r0 + k1]; al[3] = XL[r1 + k1];
#pragma unroll
            for (int t = 0; t < 8; t++) {
                const int tile = np + 2 * t;
                const int fi = (tile * 8 + ks) * 32 + lane;
                uint2 h2 = __ldg(&g_Pc_h[fi]);
                uint2 m2 = __ldg(&g_Pc_m[fi]);
                uint2 l2 = __ldg(&g_Pc_l[fi]);
                uint32_t bh[2] = { h2.x, h2.y };
                uint32_t bm[2] = { m2.x, m2.y };
                uint32_t bl[2] = { l2.x, l2.y };
                hmma(C[t], ah, bh);
                hmma(C2[t], ah, bm);
                hmma(C[t], am, bh);
                hmma(C2[t], am, bm);
                hmma(C[t], al, bh);
                hmma(C2[t], ah, bl);
            }
        }
    }
    __syncthreads();     // all x reads complete before Q overlays X
#pragma unroll
    for (int t = 0; t < 8; t++) {
        const int col = (np + 2 * t) * 8 + lc * 2;
        const int row = mt * 16 + lr;
        *reinterpret_cast<float2*>(sQ + row * PQ + col) =
            make_float2(C[t][0] + C2[t][0], C[t][1] + C2[t][1]);
        *reinterpret_cast<float2*>(sQ + (row + 8) * PQ + col) =
            make_float2(C[t][2] + C2[t][2], C[t][3] + C2[t][3]);
    }
    __syncthreads();

    // ---- phase B: logits + branchless top-2; 4 rows per K pass ----
    const int h = wid >> 1, c0 = h * 16, nb = (wid & 1) * 64;
    const float* bmh = g_bm + ((((b & 63) << 3) + h) << 14);
    float* xoB = g_xo + (b << 14);

    for (int g = 0; g < 16; g++) {
        const int n = nb + g * 4;
        float4 qa[4][4];
#pragma unroll
        for (int r = 0; r < 4; r++)
#pragma unroll
            for (int u = 0; u < 4; u++)
                qa[r][u] = *reinterpret_cast<const float4*>(&sQ[(n + r) * PQ + c0 + u * 4]);

        float sc[4][4];
        float m1[4], m2[4];
        int i1[4], i2[4];
#pragma unroll
        for (int r = 0; r < 4; r++) { m1[r] = -3e38f; m2[r] = -3e38f; i1[r] = 0; i2[r] = 0; }

#pragma unroll
        for (int jj = 0; jj < 4; jj++) {
            const int j = jj * 32 + lane;
            const float2* kr = reinterpret_cast<const float2*>(sK + j * PK + c0);
            float2 k0 = kr[0], k1 = kr[1], k2 = kr[2], k3 = kr[3];
            float2 k4 = kr[4], k5 = kr[5], k6 = kr[6], k7 = kr[7];
#pragma unroll
            for (int r = 0; r < 4; r++) {
                float s = bmh[((n + r) << 7) + j];
                s = fmaf(qa[r][0].x, k0.x, s); s = fmaf(qa[r][0].y, k0.y, s);
                s = fmaf(qa[r][0].z, k1.x, s); s = fmaf(qa[r][0].w, k1.y, s);
                s = fmaf(qa[r][1].x, k2.x, s); s = fmaf(qa[r][1].y, k2.y, s);
                s = fmaf(qa[r][1].z, k3.x, s); s = fmaf(qa[r][1].w, k3.y, s);
                s = fmaf(qa[r][2].x, k4.x, s); s = fmaf(qa[r][2].y, k4.y, s);
                s = fmaf(qa[r][2].z, k5.x, s); s = fmaf(qa[r][2].w, k5.y, s);
                s = fmaf(qa[r][3].x, k6.x, s); s = fmaf(qa[r][3].y, k6.y, s);
                s = fmaf(qa[r][3].z, k7.x, s); s = fmaf(qa[r][3].w, k7.y, s);
                sc[r][jj] = s;
                bool g1 = s > m1[r], g2 = s > m2[r];
                float om1 = m1[r]; int oi1 = i1[r];
                m2[r] = g1 ? om1 : (g2 ? s : m2[r]);
                i2[r] = g1 ? oi1 : (g2 ? j : i2[r]);
                m1[r] = g1 ? s : om1;
                i1[r] = g1 ? j : oi1;
            }
        }
#pragma unroll
        for (int r = 0; r < 4; r++) {
            float a1 = m1[r], a2 = m2[r];
            int ai1 = i1[r], ai2 = i2[r];
#pragma unroll
            for (int off = 16; off; off >>= 1) {
                float b1 = __shfl_xor_sync(0xFFFFFFFFu, a1, off);
                int  bi1 = __shfl_xor_sync(0xFFFFFFFFu, ai1, off);
                float b2 = __shfl_xor_sync(0xFFFFFFFFu, a2, off);
                int  bi2 = __shfl_xor_sync(0xFFFFFFFFu, ai2, off);
                bool agt = (a1 > b1) || (a1 == b1 && ai1 < bi1);
                float w2 = agt ? a2 : b2; int wi2 = agt ? ai2 : bi2;
                float l1 = agt ? b1 : a1; int li1 = agt ? bi1 : ai1;
                a1 = agt ? a1 : b1; ai1 = agt ? ai1 : bi1;
                bool s2 = (w2 > l1) || (w2 == l1 && wi2 < li1);
                a2 = s2 ? w2 : l1; ai2 = s2 ? wi2 : li1;
            }
            float z = __expf(sc[r][0] - a1) + __expf(sc[r][1] - a1)
                    + __expf(sc[r][2] - a1) + __expf(sc[r][3] - a1);
#pragma unroll
            for (int off = 16; off; off >>= 1)
                z += __shfl_xor_sync(0xFFFFFFFFu, z, off);
            float inv = 1.0f / z;
            float p2 = __expf(a2 - a1) * inv;
            if (lane < 16) {
                float val = fmaf(inv, sV[ai1 * PV + c0 + lane], p2 * sV[ai2 * PV + c0 + lane]);
                xoB[((n + r) << 7) + c0 + lane] = val;
            }
        }
    }
}

// ---------------- output projection (HMMA, R7-exact) ----------------
#define PPX 68
#define PROJ_XL 34816
#define PROJ_SMEM 69632

__global__ __launch_bounds__(512, 2)
void proj_kernel(const float* __restrict__ bp, float* __restrict__ out) {
    extern __shared__ char sm[];
    uint32_t* XH = reinterpret_cast<uint32_t*>(sm);
    uint32_t* XL = reinterpret_cast<uint32_t*>(sm + PROJ_XL);
    const int b = blockIdx.x, tid = threadIdx.x;
    const int wid = tid >> 5, lane = tid & 31;

    const float* xb = g_xo + (b << 14);
    for (int p = tid; p < 8192; p += 512) {
        int row = p >> 6, kp = p & 63;
        float2 v = *reinterpret_cast<const float2*>(xb + row * 128 + kp * 2);
        unsigned short h0, m0, l0, h1, m1, l1;
        split3s(v.x, h0, m0, l0);
        split3s(v.y, h1, m1, l1);
        XH[row * PPX + kp] = (uint32_t)h0 | ((uint32_t)h1 << 16);
        XL[row * PPX + kp] = (uint32_t)m0 | ((uint32_t)m1 << 16);
    }
    __syncthreads();

    const int mt = wid & 7, np = wid >> 3, lr = lane >> 2, lc = lane & 3;
    const int arow = (mt * 16 + lr) * PPX;

    float C[8][4];
#pragma unroll
    for (int t = 0; t < 8; t++) { C[t][0] = C[t][1] = C[t][2] = C[t][3] = 0.f; }
#pragma unroll 2
    for (int ks = 0; ks < 8; ks++) {
        const int ai = arow + ks * 8 + lc;
        uint32_t ah[4], al[4];
        ah[0] = XH[ai];     ah[1] = XH[ai + 8 * PPX];
        ah[2] = XH[ai + 4]; ah[3] = XH[ai + 8 * PPX + 4];
        al[0] = XL[ai];     al[1] = XL[ai + 8 * PPX];
        al[2] = XL[ai + 4]; al[3] = XL[ai + 8 * PPX + 4];
#pragma unroll
        for (int t = 0; t < 8; t++) {
            const int tile = np + 2 * t;
            const int fi = (tile * 8 + ks) * 32 + lane;
            uint2 h2 = __ldg(&g_Pp_h[fi]);
            uint2 m2 = __ldg(&g_Pp_m[fi]);
            uint32_t bh[2] = { h2.x, h2.y };
            uint32_t bm[2] = { m2.x, m2.y };
            hmma(C[t], ah, bh);
            hmma(C[t], ah, bm);
            hmma(C[t], al, bh);
        }
    }
    float* outB = out + (b << 14);
#pragma unroll
    for (int t = 0; t < 8; t++) {
        const int col = (np + 2 * t) * 8 + lc * 2;
        const int row = mt * 16 + lr;
        const float b0 = __ldg(bp + col), b1 = __ldg(bp + col + 1);
        *reinterpret_cast<float2*>(outB + row * 128 + col) = make_float2(C[t][0] + b0, C[t][1] + b1);
        *reinterpret_cast<float2*>(outB + (row + 8) * 128 + col) = make_float2(C[t][2] + b0, C[t][3] + b1);
    }
}

// ---------------------------------------------------------------------------
extern "C" void kernel_launch(void* const* d_in, const int* in_sizes, int n_in,
                              void* d_out, int out_size) {
    const float* x    = (const float*)d_in[0];
    const float* mask = (const float*)d_in[1];
    const float* Wq   = (const float*)d_in[2];
    const float* Wkv  = (const float*)d_in[3];
    const float* Wp   = (const float*)d_in[4];
    const float* bp   = (const float*)d_in[5];
    const float* tbl  = (const float*)d_in[6];
    const int*   rel  = (const int*)d_in[7];
    float* out = (float*)d_out;

    prep_w<<<32, 512>>>(Wq, Wkv, Wp);
    prep_bm<<<2048, 512>>>(mask, tbl, rel);

    cudaFuncSetAttribute(attn_kernel, cudaFuncAttributeMaxDynamicSharedMemorySize, ATTN_SMEM);
    attn_kernel<<<B_TOT, 512, ATTN_SMEM>>>(x);

    cudaFuncSetAttribute(proj_kernel, cudaFuncAttributeMaxDynamicSharedMemorySize, PROJ_SMEM);
    proj_kernel<<<B_TOT, 512, PROJ_SMEM>>>(bp, out);
}

// round 14
// speedup vs baseline: 1.9564x; 1.0080x over previous
#include <cuda_runtime.h>
#include <cuda_bf16.h>
#include <cstdint>

#define B_TOT 1024
#define NW 64

__device__ float g_bm[NW * 8 * 128 * 128];      // bias+mask [w][h][n][j]  (32MB)
__device__ float g_xo[B_TOT * 128 * 128];       // attn output fp32 staging (64MB)
// packed weight fragments: [tile][ks][lane] -> {pair kp, pair kp+4}
__device__ uint2 g_Pc_h[48 * 8 * 32];           // qkv combined W^T, 3-way split
__device__ uint2 g_Pc_m[48 * 8 * 32];
__device__ uint2 g_Pc_l[48 * 8 * 32];
__device__ uint2 g_Pp_h[16 * 8 * 32];           // proj W^T, 2-way split
__device__ uint2 g_Pp_m[16 * 8 * 32];

__device__ __forceinline__ unsigned short bfb(__nv_bfloat16 h) { return *reinterpret_cast<unsigned short*>(&h); }

__device__ __forceinline__ void split3s(float v, unsigned short& h, unsigned short& m, unsigned short& l) {
    __nv_bfloat16 bh = __float2bfloat16(v);
    float r1 = v - __bfloat162float(bh);
    __nv_bfloat16 bm = __float2bfloat16(r1);
    float r2 = r1 - __bfloat162float(bm);
    h = bfb(bh); m = bfb(bm); l = bfb(__float2bfloat16(r2));
}

__device__ __forceinline__ void hmma(float* d, const uint32_t* a, const uint32_t* b) {
    asm volatile("mma.sync.aligned.m16n8k16.row.col.f32.bf16.bf16.f32 "
                 "{%0,%1,%2,%3},{%4,%5,%6,%7},{%8,%9},{%0,%1,%2,%3};"
                 : "+f"(d[0]), "+f"(d[1]), "+f"(d[2]), "+f"(d[3])
                 : "r"(a[0]), "r"(a[1]), "r"(a[2]), "r"(a[3]), "r"(b[0]), "r"(b[1]));
}

// packed f32x2 helpers (sm_100+ base feature)
__device__ __forceinline__ void fma2(uint64_t& d, uint64_t a, uint64_t b) {
    asm("fma.rn.f32x2 %0, %1, %2, %0;" : "+l"(d) : "l"(a), "l"(b));
}
__device__ __forceinline__ uint64_t pack2(float lo, float hi) {
    uint64_t r;
    asm("mov.b64 %0, {%1, %2};" : "=l"(r) : "f"(lo), "f"(hi));
    return r;
}
__device__ __forceinline__ float sum2(uint64_t p) {
    float lo, hi;
    asm("mov.b64 {%0, %1}, %2;" : "=f"(lo), "=f"(hi) : "l"(p));
    return lo + hi;
}

// ---------------- prep ----------------
__global__ void prep_bm(const float* __restrict__ mask, const float* __restrict__ tbl,
                        const int* __restrict__ rel) {
    int t = blockIdx.x * blockDim.x + threadIdx.x;
    if (t >= NW * 16384) return;
    int w = t >> 14, nj = t & 16383;
    int r = rel[nj];
    float mk = mask[t];
#pragma unroll
    for (int h = 0; h < 8; h++)
        g_bm[(((w << 3) + h) << 14) + nj] = tbl[r * 8 + h] + mk;
}

__global__ void prep_w(const float* __restrict__ Wq, const float* __restrict__ Wkv,
                       const float* __restrict__ Wp) {
    int t = blockIdx.x * blockDim.x + threadIdx.x;   // < 16384
    int lane = t & 31, rest = t >> 5;
    int ks = rest & 7, tile = rest >> 3;
    int lr = lane >> 2, lc = lane & 3;
    int kb = ks * 16 + lc * 2;
    int kk[4] = { kb, kb + 1, kb + 8, kb + 9 };
    if (tile < 48) {
        int n = tile * 8 + lr;
        unsigned short h[4], m[4], l[4];
#pragma unroll
        for (int i = 0; i < 4; i++) {
            int k = kk[i];
            float v = (n < 128) ? Wq[k * 128 + n] * 0.25f : Wkv[k * 256 + (n - 128)];
            split3s(v, h[i], m[i], l[i]);
        }
        int idx = (tile * 8 + ks) * 32 + lane;
        g_Pc_h[idx] = make_uint2((uint32_t)h[0] | ((uint32_t)h[1] << 16),
                                 (uint32_t)h[2] | ((uint32_t)h[3] << 16));
        g_Pc_m[idx] = make_uint2((uint32_t)m[0] | ((uint32_t)m[1] << 16),
                                 (uint32_t)m[2] | ((uint32_t)m[3] << 16));
        g_Pc_l[idx] = make_uint2((uint32_t)l[0] | ((uint32_t)l[1] << 16),
                                 (uint32_t)l[2] | ((uint32_t)l[3] << 16));
    } else if (tile < 64) {
        int n = (tile - 48) * 8 + lr;
        unsigned short h[4], m[4], l[4];
#pragma unroll
        for (int i = 0; i < 4; i++)
            split3s(Wp[kk[i] * 128 + n], h[i], m[i], l[i]);
        int idx = ((tile - 48) * 8 + ks) * 32 + lane;
        g_Pp_h[idx] = make_uint2((uint32_t)h[0] | ((uint32_t)h[1] << 16),
                                 (uint32_t)h[2] | ((uint32_t)h[3] << 16));
        g_Pp_m[idx] = make_uint2((uint32_t)m[0] | ((uint32_t)m[1] << 16),
                                 (uint32_t)m[2] | ((uint32_t)m[3] << 16));
    }
}

// ---------------- fully fused attention + projection (512 threads) ----------------
// smem bytes: XH@0 XM@32768 XL@65536 (u32[128][64], swizzled)
//             K@98304 (f32 pitch130, 66560B)  V@164864 (same)   total 231424
// Q overlays X region after phase A (f32 pitch132, 67584B)
// proj phase reuses X region: PH@0 PL@34816 (u32[128][68])
#define SM_XM 32768
#define SM_XL 65536
#define SM_K  98304
#define SM_V  164864
#define ATTN_SMEM 231424
#define PQ 132
#define PK 130
#define PV 130
#define PPX 68

__global__ __launch_bounds__(512, 1)
void attn_kernel(const float* __restrict__ x, const float* __restrict__ bp,
                 float* __restrict__ out) {
    extern __shared__ char sm[];
    uint32_t* XH = reinterpret_cast<uint32_t*>(sm);
    uint32_t* XM = reinterpret_cast<uint32_t*>(sm + SM_XM);
    uint32_t* XL = reinterpret_cast<uint32_t*>(sm + SM_XL);
    float* sQ = reinterpret_cast<float*>(sm);
    float* sK = reinterpret_cast<float*>(sm + SM_K);
    float* sV = reinterpret_cast<float*>(sm + SM_V);

    const int b = blockIdx.x, tid = threadIdx.x;
    const int wid = tid >> 5, lane = tid & 31;

    // stage x -> 3-way bf16 split, swizzled pitch 64
    const float* xb = x + b * 16384;
    for (int p = tid; p < 8192; p += 512) {
        int row = p >> 6, kp = p & 63;
        float2 v = *reinterpret_cast<const float2*>(xb + row * 128 + kp * 2);
        unsigned short h0, m0, l0, h1, m1, l1;
        split3s(v.x, h0, m0, l0);
        split3s(v.y, h1, m1, l1);
        int idx = row * 64 + (kp ^ ((row & 7) << 2));
        XH[idx] = (uint32_t)h0 | ((uint32_t)h1 << 16);
        XM[idx] = (uint32_t)m0 | ((uint32_t)m1 << 16);
        XL[idx] = (uint32_t)l0 | ((uint32_t)l1 << 16);
    }
    __syncthreads();

    // ---- phase A: QKV GEMM via HMMA; 16 warps = mt(8) x np(2), 8 tiles/warp/grp
    const int mt = wid & 7, np = wid >> 3, lr = lane >> 2, lc = lane & 3;
    const int sw = lr << 2;
    const int r0 = (mt * 16 + lr) * 64;
    const int r1 = r0 + 8 * 64;

    float C[8][4], C2[8][4];

    // grp 0 = K (6 products), grp 1 = V (3 products)
#pragma unroll
    for (int grp = 0; grp < 2; grp++) {
        const int ibase = (grp == 0) ? 8 : 16;
#pragma unroll
        for (int t = 0; t < 8; t++) {
            C[t][0] = C[t][1] = C[t][2] = C[t][3] = 0.f;
            C2[t][0] = C2[t][1] = C2[t][2] = C2[t][3] = 0.f;
        }
#pragma unroll 2
        for (int ks = 0; ks < 8; ks++) {
            const int k0 = (ks * 8 + lc) ^ sw;
            const int k1 = (ks * 8 + lc + 4) ^ sw;
            uint32_t ah[4], am[4], al[4];
            ah[0] = XH[r0 + k0]; ah[1] = XH[r1 + k0]; ah[2] = XH[r0 + k1]; ah[3] = XH[r1 + k1];
            am[0] = XM[r0 + k0]; am[1] = XM[r1 + k0]; am[2] = XM[r0 + k1]; am[3] = XM[r1 + k1];
            if (grp == 0) {
                al[0] = XL[r0 + k0]; al[1] = XL[r1 + k0]; al[2] = XL[r0 + k1]; al[3] = XL[r1 + k1];
            }
#pragma unroll
            for (int t = 0; t < 8; t++) {
                const int tile = np + 2 * (ibase + t);
                const int fi = (tile * 8 + ks) * 32 + lane;
                uint2 h2 = __ldg(&g_Pc_h[fi]);
                uint2 m2 = __ldg(&g_Pc_m[fi]);
                uint32_t bh[2] = { h2.x, h2.y };
                uint32_t bm[2] = { m2.x, m2.y };
                hmma(C[t], ah, bh);
                hmma(C2[t], ah, bm);
                hmma(C[t], am, bh);
                if (grp == 0) {
                    uint2 l2 = __ldg(&g_Pc_l[fi]);
                    uint32_t bl[2] = { l2.x, l2.y };
                    hmma(C2[t], am, bm);
                    hmma(C2[t], ah, bl);
                    hmma(C[t], al, bh);
                }
            }
        }
        float* dst = (grp == 0) ? sK : sV;
        const int pitch = (grp == 0) ? PK : PV;
        const int coff = (grp == 0) ? 128 : 256;
#pragma unroll
        for (int t = 0; t < 8; t++) {
            const int col = (np + 2 * (ibase + t)) * 8 + lc * 2 - coff;
            const int row = mt * 16 + lr;
            *reinterpret_cast<float2*>(dst + row * pitch + col) =
                make_float2(C[t][0] + C2[t][0], C[t][1] + C2[t][1]);
            *reinterpret_cast<float2*>(dst + (row + 8) * pitch + col) =
                make_float2(C[t][2] + C2[t][2], C[t][3] + C2[t][3]);
        }
    }

    // grp 2 = Q (6 products), kept in C/C2, written after sync (overlays X)
    {
#pragma unroll
        for (int t = 0; t < 8; t++) {
            C[t][0] = C[t][1] = C[t][2] = C[t][3] = 0.f;
            C2[t][0] = C2[t][1] = C2[t][2] = C2[t][3] = 0.f;
        }
#pragma unroll 2
        for (int ks = 0; ks < 8; ks++) {
            const int k0 = (ks * 8 + lc) ^ sw;
            const int k1 = (ks * 8 + lc + 4) ^ sw;
            uint32_t ah[4], am[4], al[4];
            ah[0] = XH[r0 + k0]; ah[1] = XH[r1 + k0]; ah[2] = XH[r0 + k1]; ah[3] = XH[r1 + k1];
            am[0] = XM[r0 + k0]; am[1] = XM[r1 + k0]; am[2] = XM[r0 + k1]; am[3] = XM[r1 + k1];
            al[0] = XL[r0 + k0]; al[1] = XL[r1 + k0]; al[2] = XL[r0 + k1]; al[3] = XL[r1 + k1];
#pragma unroll
            for (int t = 0; t < 8; t++) {
                const int tile = np + 2 * t;
                const int fi = (tile * 8 + ks) * 32 + lane;
                uint2 h2 = __ldg(&g_Pc_h[fi]);
                uint2 m2 = __ldg(&g_Pc_m[fi]);
                uint2 l2 = __ldg(&g_Pc_l[fi]);
                uint32_t bh[2] = { h2.x, h2.y };
                uint32_t bm[2] = { m2.x, m2.y };
                uint32_t bl[2] = { l2.x, l2.y };
                hmma(C[t], ah, bh);
                hmma(C2[t], ah, bm);
                hmma(C[t], am, bh);
                hmma(C2[t], am, bm);
                hmma(C[t], al, bh);
                hmma(C2[t], ah, bl);
            }
        }
    }
    __syncthreads();     // all x reads complete before Q overlays X
#pragma unroll
    for (int t = 0; t < 8; t++) {
        const int col = (np + 2 * t) * 8 + lc * 2;
        const int row = mt * 16 + lr;
        *reinterpret_cast<float2*>(sQ + row * PQ + col) =
            make_float2(C[t][0] + C2[t][0], C[t][1] + C2[t][1]);
        *reinterpret_cast<float2*>(sQ + (row + 8) * PQ + col) =
            make_float2(C[t][2] + C2[t][2], C[t][3] + C2[t][3]);
    }
    __syncthreads();

    // ---- phase B: logits (packed f32x2) + branchless top-2; 4 rows per K pass ----
    {
        const int h = wid >> 1, c0 = h * 16, nb = (wid & 1) * 64;
        const float* bmh = g_bm + ((((b & 63) << 3) + h) << 14);
        float* xoB = g_xo + (b << 14);

        for (int g = 0; g < 16; g++) {
            const int n = nb + g * 4;
            uint64_t q2[4][8];
#pragma unroll
            for (int r = 0; r < 4; r++)
#pragma unroll
                for (int u = 0; u < 8; u++)
                    q2[r][u] = *reinterpret_cast<const uint64_t*>(&sQ[(n + r) * PQ + c0 + 2 * u]);

            float sc[4][4];
            float m1[4], m2[4];
            int i1[4], i2[4];
#pragma unroll
            for (int r = 0; r < 4; r++) { m1[r] = -3e38f; m2[r] = -3e38f; i1[r] = 0; i2[r] = 0; }

#pragma unroll
            for (int jj = 0; jj < 4; jj++) {
                const int j = jj * 32 + lane;
                const uint64_t* kr = reinterpret_cast<const uint64_t*>(sK + j * PK + c0);
                uint64_t k2[8];
#pragma unroll
                for (int u = 0; u < 8; u++) k2[u] = kr[u];
#pragma unroll
                for (int r = 0; r < 4; r++) {
                    uint64_t p = pack2(bmh[((n + r) << 7) + j], 0.f);
#pragma unroll
                    for (int u = 0; u < 8; u++) fma2(p, q2[r][u], k2[u]);
                    float s = sum2(p);
                    sc[r][jj] = s;
                    bool g1 = s > m1[r], g2 = s > m2[r];
                    float om1 = m1[r]; int oi1 = i1[r];
                    m2[r] = g1 ? om1 : (g2 ? s : m2[r]);
                    i2[r] = g1 ? oi1 : (g2 ? j : i2[r]);
                    m1[r] = g1 ? s : om1;
                    i1[r] = g1 ? j : oi1;
                }
            }
#pragma unroll
            for (int r = 0; r < 4; r++) {
                float a1 = m1[r], a2 = m2[r];
                int ai1 = i1[r], ai2 = i2[r];
#pragma unroll
                for (int off = 16; off; off >>= 1) {
                    float b1 = __shfl_xor_sync(0xFFFFFFFFu, a1, off);
                    int  bi1 = __shfl_xor_sync(0xFFFFFFFFu, ai1, off);
                    float b2 = __shfl_xor_sync(0xFFFFFFFFu, a2, off);
                    int  bi2 = __shfl_xor_sync(0xFFFFFFFFu, ai2, off);
                    bool agt = (a1 > b1) || (a1 == b1 && ai1 < bi1);
                    float w2 = agt ? a2 : b2; int wi2 = agt ? ai2 : bi2;
                    float l1 = agt ? b1 : a1; int li1 = agt ? bi1 : ai1;
                    a1 = agt ? a1 : b1; ai1 = agt ? ai1 : bi1;
                    bool s2 = (w2 > l1) || (w2 == l1 && wi2 < li1);
                    a2 = s2 ? w2 : l1; ai2 = s2 ? wi2 : li1;
                }
                float z = __expf(sc[r][0] - a1) + __expf(sc[r][1] - a1)
                        + __expf(sc[r][2] - a1) + __expf(sc[r][3] - a1);
#pragma unroll
                for (int off = 16; off; off >>= 1)
                    z += __shfl_xor_sync(0xFFFFFFFFu, z, off);
                float inv = 1.0f / z;
                float p2 = __expf(a2 - a1) * inv;
                if (lane < 16) {
                    float val = fmaf(inv, sV[ai1 * PV + c0 + lane], p2 * sV[ai2 * PV + c0 + lane]);
                    xoB[((n + r) << 7) + c0 + lane] = val;
                }
            }
        }
    }
    __syncthreads();   // phase B global writes visible block-wide; smem all dead

    // ---- phase C: output projection (xo @ Wp + bp), xo re-read L2-hot ----
    {
        uint32_t* PH = reinterpret_cast<uint32_t*>(sm);
        uint32_t* PL = reinterpret_cast<uint32_t*>(sm + 34816);
        const float* xoB = g_xo + (b << 14);
        for (int p = tid; p < 8192; p += 512) {
            int row = p >> 6, kp = p & 63;
            float2 v = *reinterpret_cast<const float2*>(xoB + row * 128 + kp * 2);
            unsigned short h0, m0, l0, h1, m1, l1;
            split3s(v.x, h0, m0, l0);
            split3s(v.y, h1, m1, l1);
            PH[row * PPX + kp] = (uint32_t)h0 | ((uint32_t)h1 << 16);
            PL[row * PPX + kp] = (uint32_t)m0 | ((uint32_t)m1 << 16);
        }
        __syncthreads();

        const int arow = (mt * 16 + lr) * PPX;
        float D[8][4];
#pragma unroll
        for (int t = 0; t < 8; t++) { D[t][0] = D[t][1] = D[t][2] = D[t][3] = 0.f; }
#pragma unroll 2
        for (int ks = 0; ks < 8; ks++) {
            const int ai = arow + ks * 8 + lc;
            uint32_t ah[4], al[4];
            ah[0] = PH[ai];     ah[1] = PH[ai + 8 * PPX];
            ah[2] = PH[ai + 4]; ah[3] = PH[ai + 8 * PPX + 4];
            al[0] = PL[ai];     al[1] = PL[ai + 8 * PPX];
            al[2] = PL[ai + 4]; al[3] = PL[ai + 8 * PPX + 4];
#pragma unroll
            for (int t = 0; t < 8; t++) {
                const int tile = np + 2 * t;
                const int fi = (tile * 8 + ks) * 32 + lane;
                uint2 h2 = __ldg(&g_Pp_h[fi]);
                uint2 m2 = __ldg(&g_Pp_m[fi]);
                uint32_t bh[2] = { h2.x, h2.y };
                uint32_t bm[2] = { m2.x, m2.y };
                hmma(D[t], ah, bh);
                hmma(D[t], ah, bm);
                hmma(D[t], al, bh);
            }
        }
        float* outB = out + (b << 14);
#pragma unroll
        for (int t = 0; t < 8; t++) {
            const int col = (np + 2 * t) * 8 + lc * 2;
            const int row = mt * 16 + lr;
            const float b0 = __ldg(bp + col), b1 = __ldg(bp + col + 1);
            *reinterpret_cast<float2*>(outB + row * 128 + col) = make_float2(D[t][0] + b0, D[t][1] + b1);
            *reinterpret_cast<float2*>(outB + (row + 8) * 128 + col) = make_float2(D[t][2] + b0, D[t][3] + b1);
        }
    }
}

// ---------------------------------------------------------------------------
extern "C" void kernel_launch(void* const* d_in, const int* in_sizes, int n_in,
                              void* d_out, int out_size) {
    const float* x    = (const float*)d_in[0];
    const float* mask = (const float*)d_in[1];
    const float* Wq   = (const float*)d_in[2];
    const float* Wkv  = (const float*)d_in[3];
    const float* Wp   = (const float*)d_in[4];
    const float* bp   = (const float*)d_in[5];
    const float* tbl  = (const float*)d_in[6];
    const int*   rel  = (const int*)d_in[7];
    float* out = (float*)d_out;

    prep_w<<<32, 512>>>(Wq, Wkv, Wp);
    prep_bm<<<2048, 512>>>(mask, tbl, rel);

    cudaFuncSetAttribute(attn_kernel, cudaFuncAttributeMaxDynamicSharedMemorySize, ATTN_SMEM);
    attn_kernel<<<B_TOT, 512, ATTN_SMEM>>>(x, bp, out);
}

// round 15
// speedup vs baseline: 2.4288x; 1.2414x over previous
#include <cuda_runtime.h>
#include <cuda_bf16.h>
#include <cstdint>

#define B_TOT 1024
#define NW 64

__device__ float g_bm[NW * 8 * 128 * 128];      // bias+mask TRANSPOSED [w][h][j][n] (32MB)
__device__ float g_xo[B_TOT * 128 * 128];       // attn output fp32 staging (64MB)
// packed weight fragments: [tile][ks][lane] -> {pair kp, pair kp+4}
__device__ uint2 g_Pc_h[48 * 8 * 32];           // qkv combined W^T, 3-way split
__device__ uint2 g_Pc_m[48 * 8 * 32];
__device__ uint2 g_Pc_l[48 * 8 * 32];
__device__ uint2 g_Pp_h[16 * 8 * 32];           // proj W^T, 2-way split
__device__ uint2 g_Pp_m[16 * 8 * 32];

__device__ __forceinline__ unsigned short bfb(__nv_bfloat16 h) { return *reinterpret_cast<unsigned short*>(&h); }

__device__ __forceinline__ void split3s(float v, unsigned short& h, unsigned short& m, unsigned short& l) {
    __nv_bfloat16 bh = __float2bfloat16(v);
    float r1 = v - __bfloat162float(bh);
    __nv_bfloat16 bm = __float2bfloat16(r1);
    float r2 = r1 - __bfloat162float(bm);
    h = bfb(bh); m = bfb(bm); l = bfb(__float2bfloat16(r2));
}

__device__ __forceinline__ void hmma(float* d, const uint32_t* a, const uint32_t* b) {
    asm volatile("mma.sync.aligned.m16n8k16.row.col.f32.bf16.bf16.f32 "
                 "{%0,%1,%2,%3},{%4,%5,%6,%7},{%8,%9},{%0,%1,%2,%3};"
                 : "+f"(d[0]), "+f"(d[1]), "+f"(d[2]), "+f"(d[3])
                 : "r"(a[0]), "r"(a[1]), "r"(a[2]), "r"(a[3]), "r"(b[0]), "r"(b[1]));
}

// packed f32x2 helpers (sm_100+ base feature)
__device__ __forceinline__ void fma2(uint64_t& d, uint64_t a, uint64_t b) {
    asm("fma.rn.f32x2 %0, %1, %2, %0;" : "+l"(d) : "l"(a), "l"(b));
}
__device__ __forceinline__ uint64_t pack2(float lo, float hi) {
    uint64_t r;
    asm("mov.b64 %0, {%1, %2};" : "=l"(r) : "f"(lo), "f"(hi));
    return r;
}
__device__ __forceinline__ float sum2(uint64_t p) {
    float lo, hi;
    asm("mov.b64 {%0, %1}, %2;" : "=f"(lo), "=f"(hi) : "l"(p));
    return lo + hi;
}

// ---------------- prep: transpose bias+mask to [w][h][j][n] ----------------
__global__ __launch_bounds__(256)
void prep_bm(const float* __restrict__ mask, const float* __restrict__ tbl,
             const int* __restrict__ rel) {
    __shared__ float msm[32][33];
    __shared__ int   rsm[32][33];
    const int w = blockIdx.x >> 4;
    const int tile = blockIdx.x & 15;
    const int nt = tile >> 2, jt = tile & 3;
    const int tx = threadIdx.x & 31, ty = threadIdx.x >> 5;   // ty 0..7

    for (int i = ty; i < 32; i += 8) {
        int n = nt * 32 + i, j = jt * 32 + tx;
        msm[i][tx] = mask[w * 16384 + n * 128 + j];
        rsm[i][tx] = rel[n * 128 + j];
    }
    __syncthreads();
#pragma unroll
    for (int h = 0; h < 8; h++)
        for (int i = ty; i < 32; i += 8) {
            int j = jt * 32 + i;
            g_bm[(((w << 3) + h) << 14) + j * 128 + nt * 32 + tx] =
                tbl[rsm[tx][i] * 8 + h] + msm[tx][i];
        }
}

__global__ void prep_w(const float* __restrict__ Wq, const float* __restrict__ Wkv,
                       const float* __restrict__ Wp) {
    int t = blockIdx.x * blockDim.x + threadIdx.x;   // < 16384
    int lane = t & 31, rest = t >> 5;
    int ks = rest & 7, tile = rest >> 3;
    int lr = lane >> 2, lc = lane & 3;
    int kb = ks * 16 + lc * 2;
    int kk[4] = { kb, kb + 1, kb + 8, kb + 9 };
    if (tile < 48) {
        int n = tile * 8 + lr;
        unsigned short h[4], m[4], l[4];
#pragma unroll
        for (int i = 0; i < 4; i++) {
            int k = kk[i];
            float v = (n < 128) ? Wq[k * 128 + n] * 0.25f : Wkv[k * 256 + (n - 128)];
            split3s(v, h[i], m[i], l[i]);
        }
        int idx = (tile * 8 + ks) * 32 + lane;
        g_Pc_h[idx] = make_uint2((uint32_t)h[0] | ((uint32_t)h[1] << 16),
                                 (uint32_t)h[2] | ((uint32_t)h[3] << 16));
        g_Pc_m[idx] = make_uint2((uint32_t)m[0] | ((uint32_t)m[1] << 16),
                                 (uint32_t)m[2] | ((uint32_t)m[3] << 16));
        g_Pc_l[idx] = make_uint2((uint32_t)l[0] | ((uint32_t)l[1] << 16),
                                 (uint32_t)l[2] | ((uint32_t)l[3] << 16));
    } else if (tile < 64) {
        int n = (tile - 48) * 8 + lr;
        unsigned short h[4], m[4], l[4];
#pragma unroll
        for (int i = 0; i < 4; i++)
            split3s(Wp[kk[i] * 128 + n], h[i], m[i], l[i]);
        int idx = ((tile - 48) * 8 + ks) * 32 + lane;
        g_Pp_h[idx] = make_uint2((uint32_t)h[0] | ((uint32_t)h[1] << 16),
                                 (uint32_t)h[2] | ((uint32_t)h[3] << 16));
        g_Pp_m[idx] = make_uint2((uint32_t)m[0] | ((uint32_t)m[1] << 16),
                                 (uint32_t)m[2] | ((uint32_t)m[3] << 16));
    }
}

// ---------------- fully fused attention + projection (512 threads) ----------------
#define SM_XM 32768
#define SM_XL 65536
#define SM_K  98304
#define SM_V  164864
#define ATTN_SMEM 231424
#define PQ 132
#define PK 130
#define PV 130
#define PPX 68

__global__ __launch_bounds__(512, 1)
void attn_kernel(const float* __restrict__ x, const float* __restrict__ bp,
                 float* __restrict__ out) {
    extern __shared__ char sm[];
    uint32_t* XH = reinterpret_cast<uint32_t*>(sm);
    uint32_t* XM = reinterpret_cast<uint32_t*>(sm + SM_XM);
    uint32_t* XL = reinterpret_cast<uint32_t*>(sm + SM_XL);
    float* sQ = reinterpret_cast<float*>(sm);
    float* sK = reinterpret_cast<float*>(sm + SM_K);
    float* sV = reinterpret_cast<float*>(sm + SM_V);

    const int b = blockIdx.x, tid = threadIdx.x;
    const int wid = tid >> 5, lane = tid & 31;

    // stage x -> 3-way bf16 split, swizzled pitch 64
    const float* xb = x + b * 16384;
    for (int p = tid; p < 8192; p += 512) {
        int row = p >> 6, kp = p & 63;
        float2 v = *reinterpret_cast<const float2*>(xb + row * 128 + kp * 2);
        unsigned short h0, m0, l0, h1, m1, l1;
        split3s(v.x, h0, m0, l0);
        split3s(v.y, h1, m1, l1);
        int idx = row * 64 + (kp ^ ((row & 7) << 2));
        XH[idx] = (uint32_t)h0 | ((uint32_t)h1 << 16);
        XM[idx] = (uint32_t)m0 | ((uint32_t)m1 << 16);
        XL[idx] = (uint32_t)l0 | ((uint32_t)l1 << 16);
    }
    __syncthreads();

    // ---- phase A ----
    const int mt = wid & 7, np = wid >> 3, lr = lane >> 2, lc = lane & 3;
    const int sw = lr << 2;
    const int r0 = (mt * 16 + lr) * 64;
    const int r1 = r0 + 8 * 64;

    // mainloop 1: Q (tiles np+2*0..7) + K (tiles np+2*8..15), 6 products each
    float C[16][4];
#pragma unroll
    for (int i = 0; i < 16; i++) { C[i][0] = C[i][1] = C[i][2] = C[i][3] = 0.f; }
#pragma unroll 2
    for (int ks = 0; ks < 8; ks++) {
        const int k0 = (ks * 8 + lc) ^ sw;
        const int k1 = (ks * 8 + lc + 4) ^ sw;
        uint32_t ah[4], am[4], al[4];
        ah[0] = XH[r0 + k0]; ah[1] = XH[r1 + k0]; ah[2] = XH[r0 + k1]; ah[3] = XH[r1 + k1];
        am[0] = XM[r0 + k0]; am[1] = XM[r1 + k0]; am[2] = XM[r0 + k1]; am[3] = XM[r1 + k1];
        al[0] = XL[r0 + k0]; al[1] = XL[r1 + k0]; al[2] = XL[r0 + k1]; al[3] = XL[r1 + k1];
#pragma unroll
        for (int i = 0; i < 16; i++) {
            const int tile = np + 2 * i;
            const int fi = (tile * 8 + ks) * 32 + lane;
            uint2 h2 = __ldg(&g_Pc_h[fi]);
            uint2 m2 = __ldg(&g_Pc_m[fi]);
            uint2 l2 = __ldg(&g_Pc_l[fi]);
            uint32_t bh[2] = { h2.x, h2.y };
            uint32_t bm[2] = { m2.x, m2.y };
            uint32_t bl[2] = { l2.x, l2.y };
            hmma(C[i], ah, bh);
            hmma(C[i], am, bh);
            hmma(C[i], ah, bm);
            hmma(C[i], am, bm);
            hmma(C[i], al, bh);
            hmma(C[i], ah, bl);
        }
    }
    // K epilogue (tiles 16..31 -> sK cols 0..127); sK region disjoint from X
#pragma unroll
    for (int i = 8; i < 16; i++) {
        const int col = (np + 2 * i) * 8 + lc * 2 - 128;
        const int row = mt * 16 + lr;
        *reinterpret_cast<float2*>(sK + row * PK + col) = make_float2(C[i][0], C[i][1]);
        *reinterpret_cast<float2*>(sK + (row + 8) * PK + col) = make_float2(C[i][2], C[i][3]);
    }

    // mainloop 2: V (tiles np+2*(16..23)), 3 products
    {
        float D[8][4];
#pragma unroll
        for (int t = 0; t < 8; t++) { D[t][0] = D[t][1] = D[t][2] = D[t][3] = 0.f; }
#pragma unroll 2
        for (int ks = 0; ks < 8; ks++) {
            const int k0 = (ks * 8 + lc) ^ sw;
            const int k1 = (ks * 8 + lc + 4) ^ sw;
            uint32_t ah[4], am[4];
            ah[0] = XH[r0 + k0]; ah[1] = XH[r1 + k0]; ah[2] = XH[r0 + k1]; ah[3] = XH[r1 + k1];
            am[0] = XM[r0 + k0]; am[1] = XM[r1 + k0]; am[2] = XM[r0 + k1]; am[3] = XM[r1 + k1];
#pragma unroll
            for (int t = 0; t < 8; t++) {
                const int tile = np + 2 * (16 + t);
                const int fi = (tile * 8 + ks) * 32 + lane;
                uint2 h2 = __ldg(&g_Pc_h[fi]);
                uint2 m2 = __ldg(&g_Pc_m[fi]);
                uint32_t bh[2] = { h2.x, h2.y };
                uint32_t bm[2] = { m2.x, m2.y };
                hmma(D[t], ah, bh);
                hmma(D[t], am, bh);
                hmma(D[t], ah, bm);
            }
        }
#pragma unroll
        for (int t = 0; t < 8; t++) {
            const int col = (np + 2 * (16 + t)) * 8 + lc * 2 - 256;
            const int row = mt * 16 + lr;
            *reinterpret_cast<float2*>(sV + row * PV + col) = make_float2(D[t][0], D[t][1]);
            *reinterpret_cast<float2*>(sV + (row + 8) * PV + col) = make_float2(D[t][2], D[t][3]);
        }
    }
    __syncthreads();     // all X reads complete before Q overlays X
#pragma unroll
    for (int i = 0; i < 8; i++) {
        const int col = (np + 2 * i) * 8 + lc * 2;
        const int row = mt * 16 + lr;
        *reinterpret_cast<float2*>(sQ + row * PQ + col) = make_float2(C[i][0], C[i][1]);
        *reinterpret_cast<float2*>(sQ + (row + 8) * PQ + col) = make_float2(C[i][2], C[i][3]);
    }
    __syncthreads();

    // ---- phase B: rows-per-lane, K broadcast, unshifted online softmax, no shuffles ----
    {
        const int h = wid >> 1, c0 = h * 16;
        const int n0 = (wid & 1) * 64 + lane;     // row A
        const int n1 = n0 + 32;                    // row B
        const float* bmt = g_bm + ((((b & 63) << 3) + h) << 14);   // [j][n]
        float* xoB = g_xo + (b << 14);

        uint64_t q0[8], q1[8];
#pragma unroll
        for (int u = 0; u < 8; u++) {
            q0[u] = *reinterpret_cast<const uint64_t*>(sQ + n0 * PQ + c0 + 2 * u);
            q1[u] = *reinterpret_cast<const uint64_t*>(sQ + n1 * PQ + c0 + 2 * u);
        }
        float m1a = -3e38f, m2a = -3e38f, za = 0.f;
        float m1b = -3e38f, m2b = -3e38f, zb = 0.f;
        int i1a = 0, i2a = 0, i1b = 0, i2b = 0;

#pragma unroll 4
        for (int j = 0; j < 128; j++) {
            const uint64_t* kr = reinterpret_cast<const uint64_t*>(sK + j * PK + c0);
            uint64_t k2[8];
#pragma unroll
            for (int u = 0; u < 8; u++) k2[u] = kr[u];   // broadcast (same addr all lanes)
            float bma = __ldg(bmt + j * 128 + n0);
            float bmb = __ldg(bmt + j * 128 + n1);

            uint64_t pa = pack2(bma, 0.f), pb = pack2(bmb, 0.f);
#pragma unroll
            for (int u = 0; u < 8; u++) { fma2(pa, q0[u], k2[u]); fma2(pb, q1[u], k2[u]); }
            float sa = sum2(pa), sb = sum2(pb);

            { bool g1 = sa > m1a, g2 = sa > m2a;
              float om = m1a; int oi = i1a;
              m2a = g1 ? om : (g2 ? sa : m2a); i2a = g1 ? oi : (g2 ? j : i2a);
              m1a = g1 ? sa : om;              i1a = g1 ? j : oi; }
            { bool g1 = sb > m1b, g2 = sb > m2b;
              float om = m1b; int oi = i1b;
              m2b = g1 ? om : (g2 ? sb : m2b); i2b = g1 ? oi : (g2 ? j : i2b);
              m1b = g1 ? sb : om;              i1b = g1 ? j : oi; }
            za += __expf(sa);
            zb += __expf(sb);
        }

        // epilogue: gather 2 V rows per owned row, write xo
#pragma unroll
        for (int r = 0; r < 2; r++) {
            const int n = r ? n1 : n0;
            const float z = r ? zb : za;
            const float w1 = __expf((r ? m1b : m1a)) / z;
            const float w2 = __expf((r ? m2b : m2a)) / z;
            const float* v1 = sV + (r ? i1b : i1a) * PV + c0;
            const float* v2 = sV + (r ? i2b : i2a) * PV + c0;
            float* dst = xoB + n * 128 + c0;
#pragma unroll
            for (int u = 0; u < 8; u++) {
                float2 a = *reinterpret_cast<const float2*>(v1 + 2 * u);
                float2 c = *reinterpret_cast<const float2*>(v2 + 2 * u);
                float2 o = make_float2(fmaf(w1, a.x, w2 * c.x), fmaf(w1, a.y, w2 * c.y));
                *reinterpret_cast<float2*>(dst + 2 * u) = o;
            }
        }
    }
    __syncthreads();   // phase B writes done; smem all dead

    // ---- phase C: output projection (xo @ Wp + bp), xo re-read L2-hot ----
    {
        uint32_t* PH = reinterpret_cast<uint32_t*>(sm);
        uint32_t* PL = reinterpret_cast<uint32_t*>(sm + 34816);
        const float* xoB = g_xo + (b << 14);
        for (int p = tid; p < 8192; p += 512) {
            int row = p >> 6, kp = p & 63;
            float2 v = *reinterpret_cast<const float2*>(xoB + row * 128 + kp * 2);
            unsigned short h0, m0, l0, h1, m1, l1;
            split3s(v.x, h0, m0, l0);
            split3s(v.y, h1, m1, l1);
            PH[row * PPX + kp] = (uint32_t)h0 | ((uint32_t)h1 << 16);
            PL[row * PPX + kp] = (uint32_t)m0 | ((uint32_t)m1 << 16);
        }
        __syncthreads();

        const int arow = (mt * 16 + lr) * PPX;
        float D[8][4];
#pragma unroll
        for (int t = 0; t < 8; t++) { D[t][0] = D[t][1] = D[t][2] = D[t][3] = 0.f; }
#pragma unroll 2
        for (int ks = 0; ks < 8; ks++) {
            const int ai = arow + ks * 8 + lc;
            uint32_t ah[4], al[4];
            ah[0] = PH[ai];     ah[1] = PH[ai + 8 * PPX];
            ah[2] = PH[ai + 4]; ah[3] = PH[ai + 8 * PPX + 4];
            al[0] = PL[ai];     al[1] = PL[ai + 8 * PPX];
            al[2] = PL[ai + 4]; al[3] = PL[ai + 8 * PPX + 4];
#pragma unroll
            for (int t = 0; t < 8; t++) {
                const int tile = np + 2 * t;
                const int fi = (tile * 8 + ks) * 32 + lane;
                uint2 h2 = __ldg(&g_Pp_h[fi]);
                uint2 m2 = __ldg(&g_Pp_m[fi]);
                uint32_t bh[2] = { h2.x, h2.y };
                uint32_t bm[2] = { m2.x, m2.y };
                hmma(D[t], ah, bh);
                hmma(D[t], ah, bm);
                hmma(D[t], al, bh);
            }
        }
        float* outB = out + (b << 14);
#pragma unroll
        for (int t = 0; t < 8; t++) {
            const int col = (np + 2 * t) * 8 + lc * 2;
            const int row = mt * 16 + lr;
            const float b0 = __ldg(bp + col), b1 = __ldg(bp + col + 1);
            *reinterpret_cast<float2*>(outB + row * 128 + col) = make_float2(D[t][0] + b0, D[t][1] + b1);
            *reinterpret_cast<float2*>(outB + (row + 8) * 128 + col) = make_float2(D[t][2] + b0, D[t][3] + b1);
        }
    }
}

// ---------------------------------------------------------------------------
extern "C" void kernel_launch(void* const* d_in, const int* in_sizes, int n_in,
                              void* d_out, int out_size) {
    const float* x    = (const float*)d_in[0];
    const float* mask = (const float*)d_in[1];
    const float* Wq   = (const float*)d_in[2];
    const float* Wkv  = (const float*)d_in[3];
    const float* Wp   = (const float*)d_in[4];
    const float* bp   = (const float*)d_in[5];
    const float* tbl  = (const float*)d_in[6];
    const int*   rel  = (const int*)d_in[7];
    float* out = (float*)d_out;

    prep_w<<<32, 512>>>(Wq, Wkv, Wp);
    prep_bm<<<1024, 256>>>(mask, tbl, rel);

    cudaFuncSetAttribute(attn_kernel, cudaFuncAttributeMaxDynamicSharedMemorySize, ATTN_SMEM);
    attn_kernel<<<B_TOT, 512, ATTN_SMEM>>>(x, bp, out);
}

// round 16
// speedup vs baseline: 2.8696x; 1.1815x over previous
#include <cuda_runtime.h>
#include <cuda_bf16.h>
#include <cstdint>

#define B_TOT 1024
#define NW 64

__device__ float g_bm[NW * 8 * 128 * 128];      // bias+mask TRANSPOSED [w][h][j][n] (32MB)
// packed weight fragments: [tile][ks][lane] -> {pair kp, pair kp+4}
__device__ uint2 g_Pc_h[48 * 8 * 32];           // qkv combined W^T, 3-way split
__device__ uint2 g_Pc_m[48 * 8 * 32];
__device__ uint2 g_Pc_l[48 * 8 * 32];
__device__ uint2 g_Pp_h[16 * 8 * 32];           // proj W^T, 2-way split
__device__ uint2 g_Pp_m[16 * 8 * 32];

__device__ __forceinline__ unsigned short bfb(__nv_bfloat16 h) { return *reinterpret_cast<unsigned short*>(&h); }

__device__ __forceinline__ void split3s(float v, unsigned short& h, unsigned short& m, unsigned short& l) {
    __nv_bfloat16 bh = __float2bfloat16(v);
    float r1 = v - __bfloat162float(bh);
    __nv_bfloat16 bm = __float2bfloat16(r1);
    float r2 = r1 - __bfloat162float(bm);
    h = bfb(bh); m = bfb(bm); l = bfb(__float2bfloat16(r2));
}
__device__ __forceinline__ void split2s(float v, unsigned short& h, unsigned short& m) {
    __nv_bfloat16 bh = __float2bfloat16(v);
    float r1 = v - __bfloat162float(bh);
    h = bfb(bh); m = bfb(__float2bfloat16(r1));
}

__device__ __forceinline__ void hmma(float* d, const uint32_t* a, const uint32_t* b) {
    asm volatile("mma.sync.aligned.m16n8k16.row.col.f32.bf16.bf16.f32 "
                 "{%0,%1,%2,%3},{%4,%5,%6,%7},{%8,%9},{%0,%1,%2,%3};"
                 : "+f"(d[0]), "+f"(d[1]), "+f"(d[2]), "+f"(d[3])
                 : "r"(a[0]), "r"(a[1]), "r"(a[2]), "r"(a[3]), "r"(b[0]), "r"(b[1]));
}

// packed f32x2 helpers (sm_100+ base feature)
__device__ __forceinline__ void fma2(uint64_t& d, uint64_t a, uint64_t b) {
    asm("fma.rn.f32x2 %0, %1, %2, %0;" : "+l"(d) : "l"(a), "l"(b));
}
__device__ __forceinline__ uint64_t pack2(float lo, float hi) {
    uint64_t r;
    asm("mov.b64 %0, {%1, %2};" : "=l"(r) : "f"(lo), "f"(hi));
    return r;
}
__device__ __forceinline__ float sum2(uint64_t p) {
    float lo, hi;
    asm("mov.b64 {%0, %1}, %2;" : "=f"(lo), "=f"(hi) : "l"(p));
    return lo + hi;
}

// ---------------- prep: transpose bias+mask to [w][h][j][n] ----------------
__global__ __launch_bounds__(256)
void prep_bm(const float* __restrict__ mask, const float* __restrict__ tbl,
             const int* __restrict__ rel) {
    __shared__ float msm[32][33];
    __shared__ int   rsm[32][33];
    const int w = blockIdx.x >> 4;
    const int tile = blockIdx.x & 15;
    const int nt = tile >> 2, jt = tile & 3;
    const int tx = threadIdx.x & 31, ty = threadIdx.x >> 5;   // ty 0..7

    for (int i = ty; i < 32; i += 8) {
        int n = nt * 32 + i, j = jt * 32 + tx;
        msm[i][tx] = mask[w * 16384 + n * 128 + j];
        rsm[i][tx] = rel[n * 128 + j];
    }
    __syncthreads();
#pragma unroll
    for (int h = 0; h < 8; h++)
        for (int i = ty; i < 32; i += 8) {
            int j = jt * 32 + i;
            g_bm[(((w << 3) + h) << 14) + j * 128 + nt * 32 + tx] =
                tbl[rsm[tx][i] * 8 + h] + msm[tx][i];
        }
}

__global__ void prep_w(const float* __restrict__ Wq, const float* __restrict__ Wkv,
                       const float* __restrict__ Wp) {
    int t = blockIdx.x * blockDim.x + threadIdx.x;   // < 16384
    int lane = t & 31, rest = t >> 5;
    int ks = rest & 7, tile = rest >> 3;
    int lr = lane >> 2, lc = lane & 3;
    int kb = ks * 16 + lc * 2;
    int kk[4] = { kb, kb + 1, kb + 8, kb + 9 };
    if (tile < 48) {
        int n = tile * 8 + lr;
        unsigned short h[4], m[4], l[4];
#pragma unroll
        for (int i = 0; i < 4; i++) {
            int k = kk[i];
            float v = (n < 128) ? Wq[k * 128 + n] * 0.25f : Wkv[k * 256 + (n - 128)];
            split3s(v, h[i], m[i], l[i]);
        }
        int idx = (tile * 8 + ks) * 32 + lane;
        g_Pc_h[idx] = make_uint2((uint32_t)h[0] | ((uint32_t)h[1] << 16),
                                 (uint32_t)h[2] | ((uint32_t)h[3] << 16));
        g_Pc_m[idx] = make_uint2((uint32_t)m[0] | ((uint32_t)m[1] << 16),
                                 (uint32_t)m[2] | ((uint32_t)m[3] << 16));
        g_Pc_l[idx] = make_uint2((uint32_t)l[0] | ((uint32_t)l[1] << 16),
                                 (uint32_t)l[2] | ((uint32_t)l[3] << 16));
    } else if (tile < 64) {
        int n = (tile - 48) * 8 + lr;
        unsigned short h[4], m[4], l[4];
#pragma unroll
        for (int i = 0; i < 4; i++)
            split3s(Wp[kk[i] * 128 + n], h[i], m[i], l[i]);
        int idx = ((tile - 48) * 8 + ks) * 32 + lane;
        g_Pp_h[idx] = make_uint2((uint32_t)h[0] | ((uint32_t)h[1] << 16),
                                 (uint32_t)h[2] | ((uint32_t)h[3] << 16));
        g_Pp_m[idx] = make_uint2((uint32_t)m[0] | ((uint32_t)m[1] << 16),
                                 (uint32_t)m[2] | ((uint32_t)m[3] << 16));
    }
}

// ---------------- fully fused attention + projection (512 threads) ----------------
#define SM_XM 32768
#define SM_XL 65536
#define SM_K  98304
#define SM_V  164864
#define ATTN_SMEM 231424
#define PQ 132
#define PK 130
#define PV 130
#define PPX 68
#define SM_PL 34816

__global__ __launch_bounds__(512, 1)
void attn_kernel(const float* __restrict__ x, const float* __restrict__ bp,
                 float* __restrict__ out) {
    extern __shared__ char sm[];
    uint32_t* XH = reinterpret_cast<uint32_t*>(sm);
    uint32_t* XM = reinterpret_cast<uint32_t*>(sm + SM_XM);
    uint32_t* XL = reinterpret_cast<uint32_t*>(sm + SM_XL);
    float* sQ = reinterpret_cast<float*>(sm);
    float* sK = reinterpret_cast<float*>(sm + SM_K);
    float* sV = reinterpret_cast<float*>(sm + SM_V);
    uint32_t* PH = reinterpret_cast<uint32_t*>(sm);            // phase B/C: split xo hi
    uint32_t* PL = reinterpret_cast<uint32_t*>(sm + SM_PL);    // phase B/C: split xo mid

    const int b = blockIdx.x, tid = threadIdx.x;
    const int wid = tid >> 5, lane = tid & 31;

    // stage x -> 3-way bf16 split, swizzled pitch 64
    const float* xb = x + b * 16384;
    for (int p = tid; p < 8192; p += 512) {
        int row = p >> 6, kp = p & 63;
        float2 v = *reinterpret_cast<const float2*>(xb + row * 128 + kp * 2);
        unsigned short h0, m0, l0, h1, m1, l1;
        split3s(v.x, h0, m0, l0);
        split3s(v.y, h1, m1, l1);
        int idx = row * 64 + (kp ^ ((row & 7) << 2));
        XH[idx] = (uint32_t)h0 | ((uint32_t)h1 << 16);
        XM[idx] = (uint32_t)m0 | ((uint32_t)m1 << 16);
        XL[idx] = (uint32_t)l0 | ((uint32_t)l1 << 16);
    }
    __syncthreads();

    // ---- phase A ----
    const int mt = wid & 7, np = wid >> 3, lr = lane >> 2, lc = lane & 3;
    const int sw = lr << 2;
    const int r0 = (mt * 16 + lr) * 64;
    const int r1 = r0 + 8 * 64;

    // mainloop 1: Q (tiles np+2*0..7) + K (tiles np+2*8..15), 6 products each
    float C[16][4];
#pragma unroll
    for (int i = 0; i < 16; i++) { C[i][0] = C[i][1] = C[i][2] = C[i][3] = 0.f; }
#pragma unroll 2
    for (int ks = 0; ks < 8; ks++) {
        const int k0 = (ks * 8 + lc) ^ sw;
        const int k1 = (ks * 8 + lc + 4) ^ sw;
        uint32_t ah[4], am[4], al[4];
        ah[0] = XH[r0 + k0]; ah[1] = XH[r1 + k0]; ah[2] = XH[r0 + k1]; ah[3] = XH[r1 + k1];
        am[0] = XM[r0 + k0]; am[1] = XM[r1 + k0]; am[2] = XM[r0 + k1]; am[3] = XM[r1 + k1];
        al[0] = XL[r0 + k0]; al[1] = XL[r1 + k0]; al[2] = XL[r0 + k1]; al[3] = XL[r1 + k1];
#pragma unroll
        for (int i = 0; i < 16; i++) {
            const int tile = np + 2 * i;
            const int fi = (tile * 8 + ks) * 32 + lane;
            uint2 h2 = __ldg(&g_Pc_h[fi]);
            uint2 m2 = __ldg(&g_Pc_m[fi]);
            uint2 l2 = __ldg(&g_Pc_l[fi]);
            uint32_t bh[2] = { h2.x, h2.y };
            uint32_t bm[2] = { m2.x, m2.y };
            uint32_t bl[2] = { l2.x, l2.y };
            hmma(C[i], ah, bh);
            hmma(C[i], am, bh);
            hmma(C[i], ah, bm);
            hmma(C[i], am, bm);
            hmma(C[i], al, bh);
            hmma(C[i], ah, bl);
        }
    }
    // K epilogue (tiles 16..31 -> sK cols 0..127); sK region disjoint from X
#pragma unroll
    for (int i = 8; i < 16; i++) {
        const int col = (np + 2 * i) * 8 + lc * 2 - 128;
        const int row = mt * 16 + lr;
        *reinterpret_cast<float2*>(sK + row * PK + col) = make_float2(C[i][0], C[i][1]);
        *reinterpret_cast<float2*>(sK + (row + 8) * PK + col) = make_float2(C[i][2], C[i][3]);
    }

    // mainloop 2: V (tiles np+2*(16..23)), 3 products
    {
        float D[8][4];
#pragma unroll
        for (int t = 0; t < 8; t++) { D[t][0] = D[t][1] = D[t][2] = D[t][3] = 0.f; }
#pragma unroll 2
        for (int ks = 0; ks < 8; ks++) {
            const int k0 = (ks * 8 + lc) ^ sw;
            const int k1 = (ks * 8 + lc + 4) ^ sw;
            uint32_t ah[4], am[4];
            ah[0] = XH[r0 + k0]; ah[1] = XH[r1 + k0]; ah[2] = XH[r0 + k1]; ah[3] = XH[r1 + k1];
            am[0] = XM[r0 + k0]; am[1] = XM[r1 + k0]; am[2] = XM[r0 + k1]; am[3] = XM[r1 + k1];
#pragma unroll
            for (int t = 0; t < 8; t++) {
                const int tile = np + 2 * (16 + t);
                const int fi = (tile * 8 + ks) * 32 + lane;
                uint2 h2 = __ldg(&g_Pc_h[fi]);
                uint2 m2 = __ldg(&g_Pc_m[fi]);
                uint32_t bh[2] = { h2.x, h2.y };
                uint32_t bm[2] = { m2.x, m2.y };
                hmma(D[t], ah, bh);
                hmma(D[t], am, bh);
                hmma(D[t], ah, bm);
            }
        }
#pragma unroll
        for (int t = 0; t < 8; t++) {
            const int col = (np + 2 * (16 + t)) * 8 + lc * 2 - 256;
            const int row = mt * 16 + lr;
            *reinterpret_cast<float2*>(sV + row * PV + col) = make_float2(D[t][0], D[t][1]);
            *reinterpret_cast<float2*>(sV + (row + 8) * PV + col) = make_float2(D[t][2], D[t][3]);
        }
    }
    __syncthreads();     // all X reads complete before Q overlays X
#pragma unroll
    for (int i = 0; i < 8; i++) {
        const int col = (np + 2 * i) * 8 + lc * 2;
        const int row = mt * 16 + lr;
        *reinterpret_cast<float2*>(sQ + row * PQ + col) = make_float2(C[i][0], C[i][1]);
        *reinterpret_cast<float2*>(sQ + (row + 8) * PQ + col) = make_float2(C[i][2], C[i][3]);
    }
    __syncthreads();

    // ---- phase B: rows-per-lane (2 consecutive rows), K broadcast, no shuffles ----
    {
        const int h = wid >> 1, c0 = h * 16;
        const int n0 = (wid & 1) * 64 + 2 * lane;  // row A
        const int n1 = n0 + 1;                      // row B
        const float* bmt = g_bm + ((((b & 63) << 3) + h) << 14);   // [j][n]

        uint64_t q0[8], q1[8];
#pragma unroll
        for (int u = 0; u < 8; u++) {
            q0[u] = *reinterpret_cast<const uint64_t*>(sQ + n0 * PQ + c0 + 2 * u);
            q1[u] = *reinterpret_cast<const uint64_t*>(sQ + n1 * PQ + c0 + 2 * u);
        }
        __syncthreads();   // all q reads done before any epilogue PH/PL write (sQ overlay)

        float m1a = -3e38f, m2a = -3e38f, za = 0.f;
        float m1b = -3e38f, m2b = -3e38f, zb = 0.f;
        int i1a = 0, i2a = 0, i1b = 0, i2b = 0;

#pragma unroll 4
        for (int j = 0; j < 128; j++) {
            const uint64_t* kr = reinterpret_cast<const uint64_t*>(sK + j * PK + c0);
            uint64_t k2[8];
#pragma unroll
            for (int u = 0; u < 8; u++) k2[u] = kr[u];   // broadcast (same addr all lanes)
            float2 bm2 = __ldg(reinterpret_cast<const float2*>(bmt + j * 128 + n0));

            uint64_t pa = pack2(bm2.x, 0.f), pb = pack2(bm2.y, 0.f);
#pragma unroll
            for (int u = 0; u < 8; u++) { fma2(pa, q0[u], k2[u]); fma2(pb, q1[u], k2[u]); }
            float sa = sum2(pa), sb = sum2(pb);

            { bool g1 = sa > m1a, g2 = sa > m2a;
              float om = m1a; int oi = i1a;
              m2a = g1 ? om : (g2 ? sa : m2a); i2a = g1 ? oi : (g2 ? j : i2a);
              m1a = g1 ? sa : om;              i1a = g1 ? j : oi; }
            { bool g1 = sb > m1b, g2 = sb > m2b;
              float om = m1b; int oi = i1b;
              m2b = g1 ? om : (g2 ? sb : m2b); i2b = g1 ? oi : (g2 ? j : i2b);
              m1b = g1 ? sb : om;              i1b = g1 ? j : oi; }
            za += __expf(sa);
            zb += __expf(sb);
        }

        // epilogue: weighted V rows -> split bf16 hi/mid directly into PH/PL (smem)
#pragma unroll
        for (int r = 0; r < 2; r++) {
            const int n = r ? n1 : n0;
            const float z = r ? zb : za;
            const float w1 = __expf((r ? m1b : m1a)) / z;
            const float w2 = __expf((r ? m2b : m2a)) / z;
            const float* v1 = sV + (r ? i1b : i1a) * PV + c0;
            const float* v2 = sV + (r ? i2b : i2a) * PV + c0;
            const int base = n * PPX + h * 8;
#pragma unroll
            for (int u = 0; u < 8; u++) {
                float2 a = *reinterpret_cast<const float2*>(v1 + 2 * u);
                float2 c = *reinterpret_cast<const float2*>(v2 + 2 * u);
                float ox = fmaf(w1, a.x, w2 * c.x);
                float oy = fmaf(w1, a.y, w2 * c.y);
                unsigned short hx, mx, hy, my;
                split2s(ox, hx, mx);
                split2s(oy, hy, my);
                PH[base + u] = (uint32_t)hx | ((uint32_t)hy << 16);
                PL[base + u] = (uint32_t)mx | ((uint32_t)my << 16);
            }
        }
    }
    __syncthreads();   // PH/PL complete before cross-warp reads

    // ---- phase C: output projection from smem PH/PL ----
    {
        const int arow = (mt * 16 + lr) * PPX;
        float D[8][4];
#pragma unroll
        for (int t = 0; t < 8; t++) { D[t][0] = D[t][1] = D[t][2] = D[t][3] = 0.f; }
#pragma unroll 2
        for (int ks = 0; ks < 8; ks++) {
            const int ai = arow + ks * 8 + lc;
            uint32_t ah[4], al[4];
            ah[0] = PH[ai];     ah[1] = PH[ai + 8 * PPX];
            ah[2] = PH[ai + 4]; ah[3] = PH[ai + 8 * PPX + 4];
            al[0] = PL[ai];     al[1] = PL[ai + 8 * PPX];
            al[2] = PL[ai + 4]; al[3] = PL[ai + 8 * PPX + 4];
#pragma unroll
            for (int t = 0; t < 8; t++) {
                const int tile = np + 2 * t;
                const int fi = (tile * 8 + ks) * 32 + lane;
                uint2 h2 = __ldg(&g_Pp_h[fi]);
                uint2 m2 = __ldg(&g_Pp_m[fi]);
                uint32_t bh[2] = { h2.x, h2.y };
                uint32_t bm[2] = { m2.x, m2.y };
                hmma(D[t], ah, bh);
                hmma(D[t], ah, bm);
                hmma(D[t], al, bh);
            }
        }
        float* outB = out + (b << 14);
#pragma unroll
        for (int t = 0; t < 8; t++) {
            const int col = (np + 2 * t) * 8 + lc * 2;
            const int row = mt * 16 + lr;
            const float b0 = __ldg(bp + col), b1 = __ldg(bp + col + 1);
            *reinterpret_cast<float2*>(outB + row * 128 + col) = make_float2(D[t][0] + b0, D[t][1] + b1);
            *reinterpret_cast<float2*>(outB + (row + 8) * 128 + col) = make_float2(D[t][2] + b0, D[t][3] + b1);
        }
    }
}

// ---------------------------------------------------------------------------
extern "C" void kernel_launch(void* const* d_in, const int* in_sizes, int n_in,
                              void* d_out, int out_size) {
    const float* x    = (const float*)d_in[0];
    const float* mask = (const float*)d_in[1];
    const float* Wq   = (const float*)d_in[2];
    const float* Wkv  = (const float*)d_in[3];
    const float* Wp   = (const float*)d_in[4];
    const float* bp   = (const float*)d_in[5];
    const float* tbl  = (const float*)d_in[6];
    const int*   rel  = (const int*)d_in[7];
    float* out = (float*)d_out;

    prep_w<<<32, 512>>>(Wq, Wkv, Wp);
    prep_bm<<<1024, 256>>>(mask, tbl, rel);

    cudaFuncSetAttribute(attn_kernel, cudaFuncAttributeMaxDynamicSharedMemorySize, ATTN_SMEM);
    attn_kernel<<<B_TOT, 512, ATTN_SMEM>>>(x, bp, out);
}